// round 1
// baseline (speedup 1.0000x reference)
#include <cuda_runtime.h>
#include <math.h>

// ---------------- problem constants ----------------
#define S_LEN   2048
#define HID     7168
#define NH      32
#define Q_LORA  1536
#define KV_LORA 512
#define ROPE_D  64
#define CDIM    576          // KV_LORA + ROPE_D
#define V_D     128
#define MIN_MASKED (-10000.0f)

// ---------------- scratch (static device allocations) ----------------
__device__ float g_compressed[(size_t)S_LEN * CDIM];                 //  4.7 MB
__device__ float g_qa_pre[(size_t)S_LEN * Q_LORA];                   // 12.6 MB
__device__ float g_qa[(size_t)S_LEN * Q_LORA];                       // 12.6 MB
__device__ float g_qpe[(size_t)S_LEN * (NH * ROPE_D)];               // 16.8 MB
__device__ float g_kfull[(size_t)S_LEN * CDIM];                      //  4.7 MB
__device__ float g_qfull[(size_t)NH * S_LEN * CDIM];                 //  151 MB
__device__ float g_logits[(size_t)NH * S_LEN * S_LEN];               //  537 MB
__device__ float g_ctx[(size_t)NH * S_LEN * KV_LORA];                //  134 MB
__device__ float g_attnout[(size_t)S_LEN * (NH * V_D)];              // 33.6 MB

// ---------------- generic register-blocked SGEMM ----------------
// C[M,N] = alpha * A[M,K] @ B  (+ causal logic)
//   TRANSB=false: B is [K,N] row-major
//   TRANSB=true : B is [N,K] row-major (used for Q @ K^T)
// mode 0: plain
// mode 1: causal QK^T epilogue (col > row -> MIN_MASKED; fully-masked blocks skipped)
// mode 2: P@V with K-loop limited to the causal extent of this row block
#define BM 128
#define BN 64
#define BK 8
#define TM 8
#define TN 4

template<bool TRANSB>
__global__ void __launch_bounds__(256)
sgemm_kernel(const float* __restrict__ A, const float* __restrict__ B,
             float* __restrict__ C,
             int M, int N, int K, int lda, int ldb, int ldc,
             long long sA, long long sB, long long sC,
             float alpha, int mode)
{
    const long long bz = blockIdx.z;
    A += bz * sA;  B += bz * sB;  C += bz * sC;

    const int row0 = blockIdx.y * BM;
    const int col0 = blockIdx.x * BN;
    const int tid  = threadIdx.x;
    const int tx   = tid & 15;      // 0..15  -> 4 cols each
    const int ty   = tid >> 4;      // 0..15  -> 8 rows each

    if (mode == 1 && col0 >= row0 + BM) {
        // fully above the diagonal: every (s,t) in the block has t > s
        #pragma unroll
        for (int i = 0; i < TM; i++) {
            int r = row0 + ty * TM + i;
            float* crow = C + (long long)r * ldc + col0 + tx * TN;
            crow[0] = crow[1] = crow[2] = crow[3] = MIN_MASKED;
        }
        return;
    }

    __shared__ float As[BK][BM];
    __shared__ float Bs[BK][BN];

    int kEnd = K;
    if (mode == 2) kEnd = min(K, row0 + BM);   // probs are exactly 0 beyond the diagonal

    float acc[TM][TN];
    #pragma unroll
    for (int i = 0; i < TM; i++)
        #pragma unroll
        for (int j = 0; j < TN; j++) acc[i][j] = 0.0f;

    const int aRow = tid >> 1;          // 0..127
    const int aCol = (tid & 1) * 4;     // 0 or 4

    for (int k0 = 0; k0 < kEnd; k0 += BK) {
        // A tile: [BM x BK] -> As[k][m]
        {
            float4 av = *(const float4*)(A + (long long)(row0 + aRow) * lda + k0 + aCol);
            As[aCol + 0][aRow] = av.x;
            As[aCol + 1][aRow] = av.y;
            As[aCol + 2][aRow] = av.z;
            As[aCol + 3][aRow] = av.w;
        }
        // B tile -> Bs[k][n]
        if (!TRANSB) {
            int bRow = tid >> 5;            // 0..7
            int bCol = (tid & 31) * 2;      // 0..62
            float2 bv = *(const float2*)(B + (long long)(k0 + bRow) * ldb + col0 + bCol);
            Bs[bRow][bCol]     = bv.x;
            Bs[bRow][bCol + 1] = bv.y;
        } else {
            int n  = tid >> 2;              // 0..63
            int kk = (tid & 3) * 2;         // 0,2,4,6
            float2 bv = *(const float2*)(B + (long long)(col0 + n) * ldb + k0 + kk);
            Bs[kk][n]     = bv.x;
            Bs[kk + 1][n] = bv.y;
        }
        __syncthreads();

        #pragma unroll
        for (int kk = 0; kk < BK; kk++) {
            float a[TM], b[TN];
            float4 a0 = *(const float4*)&As[kk][ty * TM];
            float4 a1 = *(const float4*)&As[kk][ty * TM + 4];
            a[0] = a0.x; a[1] = a0.y; a[2] = a0.z; a[3] = a0.w;
            a[4] = a1.x; a[5] = a1.y; a[6] = a1.z; a[7] = a1.w;
            float4 bv = *(const float4*)&Bs[kk][tx * TN];
            b[0] = bv.x; b[1] = bv.y; b[2] = bv.z; b[3] = bv.w;
            #pragma unroll
            for (int i = 0; i < TM; i++)
                #pragma unroll
                for (int j = 0; j < TN; j++)
                    acc[i][j] = fmaf(a[i], b[j], acc[i][j]);
        }
        __syncthreads();
    }

    #pragma unroll
    for (int i = 0; i < TM; i++) {
        int r = row0 + ty * TM + i;
        float* crow = C + (long long)r * ldc + col0 + tx * TN;
        if (mode == 1) {
            #pragma unroll
            for (int j = 0; j < TN; j++) {
                int cidx = col0 + tx * TN + j;
                crow[j] = (cidx > r) ? MIN_MASKED : acc[i][j] * alpha;
            }
        } else {
            float4 v = make_float4(acc[i][0] * alpha, acc[i][1] * alpha,
                                   acc[i][2] * alpha, acc[i][3] * alpha);
            *(float4*)crow = v;
        }
    }
}

// ---------------- rmsnorm(kva) + RoPE(k_pe) -> k_full ----------------
__global__ void kva_rms_rope_kernel(const float* __restrict__ comp,
                                    const float* __restrict__ kv_ln,
                                    const int*   __restrict__ pos_ids,
                                    float* __restrict__ kfull)
{
    int s = blockIdx.x;
    const float* x = comp + (long long)s * CDIM;
    float* out = kfull + (long long)s * CDIM;

    __shared__ float red[128];
    float ss = 0.0f;
    for (int i = threadIdx.x; i < KV_LORA; i += 128) { float v = x[i]; ss += v * v; }
    red[threadIdx.x] = ss; __syncthreads();
    for (int st = 64; st > 0; st >>= 1) {
        if (threadIdx.x < st) red[threadIdx.x] += red[threadIdx.x + st];
        __syncthreads();
    }
    float scale = rsqrtf(red[0] / (float)KV_LORA + 1e-6f);

    for (int i = threadIdx.x; i < KV_LORA; i += 128)
        out[i] = x[i] * scale * kv_ln[i];

    if (threadIdx.x < ROPE_D / 2) {
        int j = threadIdx.x;
        float pos  = (float)pos_ids[s];
        float invf = powf(10000.0f, -(float)(2 * j) / (float)ROPE_D);
        float ang  = pos * invf;
        float c = cosf(ang), sn = sinf(ang);
        float x0 = x[KV_LORA + 2 * j];
        float x1 = x[KV_LORA + 2 * j + 1];
        out[KV_LORA + j]               = x0 * c - x1 * sn;
        out[KV_LORA + ROPE_D / 2 + j]  = x1 * c + x0 * sn;
    }
}

// ---------------- rmsnorm(q_a) ----------------
__global__ void qa_rms_kernel(const float* __restrict__ in,
                              const float* __restrict__ w,
                              float* __restrict__ outp)
{
    int s = blockIdx.x;
    const float* x = in + (long long)s * Q_LORA;
    float* o = outp + (long long)s * Q_LORA;

    __shared__ float red[256];
    float ss = 0.0f;
    for (int i = threadIdx.x; i < Q_LORA; i += 256) { float v = x[i]; ss += v * v; }
    red[threadIdx.x] = ss; __syncthreads();
    for (int st = 128; st > 0; st >>= 1) {
        if (threadIdx.x < st) red[threadIdx.x] += red[threadIdx.x + st];
        __syncthreads();
    }
    float scale = rsqrtf(red[0] / (float)Q_LORA + 1e-6f);
    for (int i = threadIdx.x; i < Q_LORA; i += 256)
        o[i] = x[i] * scale * w[i];
}

// ---------------- RoPE on q_pe, scatter into q_full rope columns ----------------
__global__ void rope_q_kernel(const float* __restrict__ qpe,
                              const int*   __restrict__ pos_ids,
                              float* __restrict__ qfull)
{
    int s = blockIdx.x;
    int h = blockIdx.y;
    int j = threadIdx.x;            // 0..31
    float pos  = (float)pos_ids[s];
    float invf = powf(10000.0f, -(float)(2 * j) / (float)ROPE_D);
    float ang  = pos * invf;
    float c = cosf(ang), sn = sinf(ang);
    const float* x = qpe + (long long)s * (NH * ROPE_D) + h * ROPE_D;
    float x0 = x[2 * j], x1 = x[2 * j + 1];
    float* out = qfull + ((long long)h * S_LEN + s) * CDIM + KV_LORA;
    out[j]                = x0 * c - x1 * sn;
    out[j + ROPE_D / 2]   = x1 * c + x0 * sn;
}

// ---------------- row softmax over logits [NH*S, S] ----------------
__global__ void softmax_kernel(float* __restrict__ logits)
{
    long long row = blockIdx.x;
    float* p = logits + row * S_LEN;
    int tid = threadIdx.x;          // 256 threads, 8 per thread

    float v[8];
    float m = -1e30f;
    #pragma unroll
    for (int i = 0; i < 8; i++) { v[i] = p[tid + i * 256]; m = fmaxf(m, v[i]); }

    __shared__ float red[256];
    red[tid] = m; __syncthreads();
    for (int st = 128; st > 0; st >>= 1) {
        if (tid < st) red[tid] = fmaxf(red[tid], red[tid + st]);
        __syncthreads();
    }
    m = red[0]; __syncthreads();

    float sum = 0.0f;
    #pragma unroll
    for (int i = 0; i < 8; i++) { v[i] = __expf(v[i] - m); sum += v[i]; }
    red[tid] = sum; __syncthreads();
    for (int st = 128; st > 0; st >>= 1) {
        if (tid < st) red[tid] += red[tid + st];
        __syncthreads();
    }
    float inv = 1.0f / red[0];
    #pragma unroll
    for (int i = 0; i < 8; i++) p[tid + i * 256] = v[i] * inv;
}

// ---------------- host launcher ----------------
static void launch_sgemm(bool transb, const float* A, const float* B, float* C,
                         int M, int N, int K, int lda, int ldb, int ldc,
                         long long sA, long long sB, long long sC,
                         int batch, float alpha, int mode)
{
    dim3 grid(N / BN, M / BM, batch);
    if (transb)
        sgemm_kernel<true><<<grid, 256>>>(A, B, C, M, N, K, lda, ldb, ldc, sA, sB, sC, alpha, mode);
    else
        sgemm_kernel<false><<<grid, 256>>>(A, B, C, M, N, K, lda, ldb, ldc, sA, sB, sC, alpha, mode);
}

extern "C" void kernel_launch(void* const* d_in, const int* in_sizes, int n_in,
                              void* d_out, int out_size)
{
    (void)in_sizes; (void)n_in; (void)out_size;
    const float* X        = (const float*)d_in[0];   // [S, HID]
    // d_in[1] attention_mask: structurally causal triu(k=1) -> handled analytically
    const int*   pos      = (const int*)d_in[2];     // [1, S]
    const float* W_kv_a   = (const float*)d_in[3];   // [HID, CDIM]
    const float* W_q_a    = (const float*)d_in[4];   // [HID, Q_LORA]
    const float* q_ln     = (const float*)d_in[5];   // [Q_LORA]
    const float* kv_ln    = (const float*)d_in[6];   // [KV_LORA]
    const float* q_rope_w = (const float*)d_in[7];   // [Q_LORA, NH*ROPE_D]
    const float* fusedqk  = (const float*)d_in[8];   // [NH, Q_LORA, KV_LORA]
    const float* v_up     = (const float*)d_in[9];   // [NH, KV_LORA, V_D]
    const float* W_o      = (const float*)d_in[10];  // [NH*V_D, HID]
    float* out = (float*)d_out;                      // [S, HID]

    float *comp, *qa_pre, *qa, *qpe, *kfull, *qfull, *logits, *ctx, *attnout;
    cudaGetSymbolAddress((void**)&comp,    g_compressed);
    cudaGetSymbolAddress((void**)&qa_pre,  g_qa_pre);
    cudaGetSymbolAddress((void**)&qa,      g_qa);
    cudaGetSymbolAddress((void**)&qpe,     g_qpe);
    cudaGetSymbolAddress((void**)&kfull,   g_kfull);
    cudaGetSymbolAddress((void**)&qfull,   g_qfull);
    cudaGetSymbolAddress((void**)&logits,  g_logits);
    cudaGetSymbolAddress((void**)&ctx,     g_ctx);
    cudaGetSymbolAddress((void**)&attnout, g_attnout);

    const float scale = 1.0f / sqrtf((float)(KV_LORA == 512 ? 192 : 192)); // 1/sqrt(NOPE_D+ROPE_D)=1/sqrt(192)

    // 1) compressed = X @ W_kv_a                      [S, CDIM]
    launch_sgemm(false, X, W_kv_a, comp, S_LEN, CDIM, HID, HID, CDIM, CDIM, 0, 0, 0, 1, 1.0f, 0);
    // 2) qa_pre = X @ W_q_a                           [S, Q_LORA]
    launch_sgemm(false, X, W_q_a, qa_pre, S_LEN, Q_LORA, HID, HID, Q_LORA, Q_LORA, 0, 0, 0, 1, 1.0f, 0);
    // 3) k_full = concat(rmsnorm(kva), rope(k_pe))    [S, CDIM]
    kva_rms_rope_kernel<<<S_LEN, 128>>>(comp, kv_ln, pos, kfull);
    // 4) qa = rmsnorm(qa_pre)                         [S, Q_LORA]
    qa_rms_kernel<<<S_LEN, 256>>>(qa_pre, q_ln, qa);
    // 5) qpe = qa @ q_rope_w                          [S, NH*ROPE_D]
    launch_sgemm(false, qa, q_rope_w, qpe, S_LEN, NH * ROPE_D, Q_LORA,
                 Q_LORA, NH * ROPE_D, NH * ROPE_D, 0, 0, 0, 1, 1.0f, 0);
    // 6) rope(q_pe) -> q_full[:, :, 512:576]
    rope_q_kernel<<<dim3(S_LEN, NH), ROPE_D / 2>>>(qpe, pos, qfull);
    // 7) dq = qa @ fusedqk[h] -> q_full[:, :, :512]   (batched over heads)
    launch_sgemm(false, qa, fusedqk, qfull, S_LEN, KV_LORA, Q_LORA,
                 Q_LORA, KV_LORA, CDIM,
                 0, (long long)Q_LORA * KV_LORA, (long long)S_LEN * CDIM,
                 NH, 1.0f, 0);
    // 8) logits = scale * q_full @ k_full^T, causal   (batched, TRANSB)
    launch_sgemm(true, qfull, kfull, logits, S_LEN, S_LEN, CDIM,
                 CDIM, CDIM, S_LEN,
                 (long long)S_LEN * CDIM, 0, (long long)S_LEN * S_LEN,
                 NH, scale, 1);
    // 9) softmax rows
    softmax_kernel<<<NH * S_LEN, 256>>>(logits);
    // 10) ctx = probs @ kva  (V = first 512 cols of k_full, ldb=CDIM), causal K-limit
    launch_sgemm(false, logits, kfull, ctx, S_LEN, KV_LORA, S_LEN,
                 S_LEN, CDIM, KV_LORA,
                 (long long)S_LEN * S_LEN, 0, (long long)S_LEN * KV_LORA,
                 NH, 1.0f, 2);
    // 11) attnout[:, h*128:(h+1)*128] = ctx[h] @ v_up[h]
    launch_sgemm(false, ctx, v_up, attnout, S_LEN, V_D, KV_LORA,
                 KV_LORA, V_D, NH * V_D,
                 (long long)S_LEN * KV_LORA, (long long)KV_LORA * V_D, (long long)V_D,
                 NH, 1.0f, 0);
    // 12) out = attnout @ W_o                          [S, HID]
    launch_sgemm(false, attnout, W_o, out, S_LEN, HID, NH * V_D,
                 NH * V_D, HID, HID, 0, 0, 0, 1, 1.0f, 0);
}

// round 2
// speedup vs baseline: 2.6533x; 2.6533x over previous
#include <cuda_runtime.h>
#include <math.h>

// ---------------- problem constants ----------------
#define S_LEN   2048
#define HID     7168
#define NH      32
#define Q_LORA  1536
#define KV_LORA 512
#define ROPE_D  64
#define CDIM    576          // KV_LORA + ROPE_D
#define V_D     128
#define MIN_MASKED (-10000.0f)

// ---------------- scratch (static device allocations) ----------------
__device__ float g_compressed[(size_t)S_LEN * CDIM];
__device__ float g_qa_pre[(size_t)S_LEN * Q_LORA];
__device__ float g_qa[(size_t)S_LEN * Q_LORA];
__device__ float g_qpe[(size_t)S_LEN * (NH * ROPE_D)];
__device__ float g_kfull[(size_t)S_LEN * CDIM];
__device__ float g_qfull[(size_t)NH * S_LEN * CDIM];
__device__ float g_logits[(size_t)NH * S_LEN * S_LEN];
__device__ float g_ctx[(size_t)NH * S_LEN * KV_LORA];
__device__ float g_attnout[(size_t)S_LEN * (NH * V_D)];

// ---------------- TF32 tensor-core GEMM ----------------
// C[M,N] = alpha * A[M,K] @ B  (+ causal logic)
//   TRANSB=false: B is [K,N] row-major
//   TRANSB=true : B is [N,K] row-major (Q @ K^T)
// mode 0: plain; mode 1: causal epilogue (+block skip); mode 2: K limited to causal extent
#define BM 128
#define BN 128
#define BK 16
#define AS_STRIDE 20    // floats; 20g mod 32 distinct -> conflict-free A LDS
#define BS_STRIDE 136   // floats; 8k mod 32 distinct  -> conflict-free B LDS

__device__ __forceinline__ float rna_tf32(float x) {
    unsigned u;
    asm("cvt.rna.tf32.f32 %0, %1;" : "=r"(u) : "f"(x));
    return __uint_as_float(u);
}

__device__ __forceinline__ void mma_tf32(float (&c)[4], const unsigned (&a)[4], const unsigned (&b)[2]) {
    asm volatile(
        "mma.sync.aligned.m16n8k8.row.col.f32.tf32.tf32.f32 "
        "{%0,%1,%2,%3}, {%4,%5,%6,%7}, {%8,%9}, {%0,%1,%2,%3};"
        : "+f"(c[0]), "+f"(c[1]), "+f"(c[2]), "+f"(c[3])
        : "r"(a[0]), "r"(a[1]), "r"(a[2]), "r"(a[3]), "r"(b[0]), "r"(b[1]));
}

template<bool TRANSB>
__global__ void __launch_bounds__(256, 2)
gemm_tc_kernel(const float* __restrict__ A, const float* __restrict__ B,
               float* __restrict__ C,
               int M, int N, int K, int lda, int ldb, int ldc,
               long long sA, long long sB, long long sC,
               float alpha, int mode)
{
    const long long bz = blockIdx.z;
    A += bz * sA;  B += bz * sB;  C += bz * sC;

    const int row0 = blockIdx.y * BM;
    const int col0 = blockIdx.x * BN;
    const int tid  = threadIdx.x;
    const int lane = tid & 31;
    const int wid  = tid >> 5;
    const int wm   = wid >> 2;        // 0..1
    const int wn   = wid & 3;         // 0..3
    const int g    = lane >> 2;       // groupID 0..7
    const int tig  = lane & 3;        // 0..3

    if (mode == 1 && col0 >= row0 + BM) {
        // fully above diagonal
        const float4 mv = make_float4(MIN_MASKED, MIN_MASKED, MIN_MASKED, MIN_MASKED);
        for (int i = tid; i < BM * (BN / 4); i += 256) {
            int r  = i / (BN / 4);
            int cq = (i % (BN / 4)) * 4;
            *(float4*)(C + (long long)(row0 + r) * ldc + col0 + cq) = mv;
        }
        return;
    }

    __shared__ float As[BM * AS_STRIDE];
    __shared__ float Bs[BK * BS_STRIDE];

    int kEnd = K;
    if (mode == 2) kEnd = min(K, row0 + BM);

    float acc[4][4][4] = {};
    float4 aR[2], bR[2];

    auto ldA = [&](int k0) {
        #pragma unroll
        for (int e = 0; e < 2; e++) {
            int idx = tid + e * 256;
            int m = idx >> 2, kq = (idx & 3) << 2;
            aR[e] = *(const float4*)(A + (long long)(row0 + m) * lda + k0 + kq);
        }
    };
    auto ldB = [&](int k0) {
        #pragma unroll
        for (int e = 0; e < 2; e++) {
            int idx = tid + e * 256;
            if (!TRANSB) {
                int k = idx >> 5, nq = (idx & 31) << 2;
                bool in = (col0 + nq) < N;
                bR[e] = in ? *(const float4*)(B + (long long)(k0 + k) * ldb + col0 + nq)
                           : make_float4(0.f, 0.f, 0.f, 0.f);
            } else {
                int n = idx >> 2, kq = (idx & 3) << 2;
                bool in = (col0 + n) < N;
                bR[e] = in ? *(const float4*)(B + (long long)(col0 + n) * ldb + k0 + kq)
                           : make_float4(0.f, 0.f, 0.f, 0.f);
            }
        }
    };
    auto stA = [&]() {
        #pragma unroll
        for (int e = 0; e < 2; e++) {
            int idx = tid + e * 256;
            int m = idx >> 2, kq = (idx & 3) << 2;
            float4 v = aR[e];
            v.x = rna_tf32(v.x); v.y = rna_tf32(v.y);
            v.z = rna_tf32(v.z); v.w = rna_tf32(v.w);
            *(float4*)&As[m * AS_STRIDE + kq] = v;
        }
    };
    auto stB = [&]() {
        #pragma unroll
        for (int e = 0; e < 2; e++) {
            int idx = tid + e * 256;
            float4 v = bR[e];
            v.x = rna_tf32(v.x); v.y = rna_tf32(v.y);
            v.z = rna_tf32(v.z); v.w = rna_tf32(v.w);
            if (!TRANSB) {
                int k = idx >> 5, nq = (idx & 31) << 2;
                *(float4*)&Bs[k * BS_STRIDE + nq] = v;
            } else {
                int n = idx >> 2, kq = (idx & 3) << 2;
                Bs[(kq + 0) * BS_STRIDE + n] = v.x;
                Bs[(kq + 1) * BS_STRIDE + n] = v.y;
                Bs[(kq + 2) * BS_STRIDE + n] = v.z;
                Bs[(kq + 3) * BS_STRIDE + n] = v.w;
            }
        }
    };
    auto compute = [&]() {
        #pragma unroll
        for (int kk = 0; kk < BK; kk += 8) {
            unsigned af[4][4], bf[4][2];
            #pragma unroll
            for (int mi = 0; mi < 4; mi++) {
                int mb = wm * 64 + mi * 16 + g;
                af[mi][0] = __float_as_uint(As[(mb    ) * AS_STRIDE + kk + tig    ]);
                af[mi][1] = __float_as_uint(As[(mb + 8) * AS_STRIDE + kk + tig    ]);
                af[mi][2] = __float_as_uint(As[(mb    ) * AS_STRIDE + kk + tig + 4]);
                af[mi][3] = __float_as_uint(As[(mb + 8) * AS_STRIDE + kk + tig + 4]);
            }
            #pragma unroll
            for (int nj = 0; nj < 4; nj++) {
                int nb = wn * 32 + nj * 8 + g;
                bf[nj][0] = __float_as_uint(Bs[(kk + tig    ) * BS_STRIDE + nb]);
                bf[nj][1] = __float_as_uint(Bs[(kk + tig + 4) * BS_STRIDE + nb]);
            }
            #pragma unroll
            for (int mi = 0; mi < 4; mi++)
                #pragma unroll
                for (int nj = 0; nj < 4; nj++)
                    mma_tf32(acc[mi][nj], af[mi], bf[nj]);
        }
    };

    ldA(0); ldB(0);
    stA(); stB();
    __syncthreads();

    for (int k0 = 0; k0 < kEnd; k0 += BK) {
        bool nxt = (k0 + BK) < kEnd;
        if (nxt) { ldA(k0 + BK); ldB(k0 + BK); }
        compute();
        __syncthreads();
        if (nxt) { stA(); stB(); __syncthreads(); }
    }

    // epilogue
    #pragma unroll
    for (int mi = 0; mi < 4; mi++) {
        int r = row0 + wm * 64 + mi * 16 + g;
        #pragma unroll
        for (int nj = 0; nj < 4; nj++) {
            int c = col0 + wn * 32 + nj * 8 + tig * 2;
            float v0 = acc[mi][nj][0] * alpha;
            float v1 = acc[mi][nj][1] * alpha;
            float v2 = acc[mi][nj][2] * alpha;
            float v3 = acc[mi][nj][3] * alpha;
            if (mode == 1) {
                v0 = (c     > r    ) ? MIN_MASKED : v0;
                v1 = (c + 1 > r    ) ? MIN_MASKED : v1;
                v2 = (c     > r + 8) ? MIN_MASKED : v2;
                v3 = (c + 1 > r + 8) ? MIN_MASKED : v3;
            }
            if (c < N) {    // N is always even; c even -> c+1 < N too
                float* p0 = C + (long long)r * ldc + c;
                float* p1 = C + (long long)(r + 8) * ldc + c;
                p0[0] = v0; p0[1] = v1;
                p1[0] = v2; p1[1] = v3;
            }
        }
    }
}

// ---------------- rmsnorm(kva) + RoPE(k_pe) -> k_full ----------------
__global__ void kva_rms_rope_kernel(const float* __restrict__ comp,
                                    const float* __restrict__ kv_ln,
                                    const int*   __restrict__ pos_ids,
                                    float* __restrict__ kfull)
{
    int s = blockIdx.x;
    const float* x = comp + (long long)s * CDIM;
    float* out = kfull + (long long)s * CDIM;

    __shared__ float red[128];
    float ss = 0.0f;
    for (int i = threadIdx.x; i < KV_LORA; i += 128) { float v = x[i]; ss += v * v; }
    red[threadIdx.x] = ss; __syncthreads();
    for (int st = 64; st > 0; st >>= 1) {
        if (threadIdx.x < st) red[threadIdx.x] += red[threadIdx.x + st];
        __syncthreads();
    }
    float scale = rsqrtf(red[0] / (float)KV_LORA + 1e-6f);

    for (int i = threadIdx.x; i < KV_LORA; i += 128)
        out[i] = x[i] * scale * kv_ln[i];

    if (threadIdx.x < ROPE_D / 2) {
        int j = threadIdx.x;
        float pos  = (float)pos_ids[s];
        float invf = powf(10000.0f, -(float)(2 * j) / (float)ROPE_D);
        float ang  = pos * invf;
        float c = cosf(ang), sn = sinf(ang);
        float x0 = x[KV_LORA + 2 * j];
        float x1 = x[KV_LORA + 2 * j + 1];
        out[KV_LORA + j]               = x0 * c - x1 * sn;
        out[KV_LORA + ROPE_D / 2 + j]  = x1 * c + x0 * sn;
    }
}

// ---------------- rmsnorm(q_a) ----------------
__global__ void qa_rms_kernel(const float* __restrict__ in,
                              const float* __restrict__ w,
                              float* __restrict__ outp)
{
    int s = blockIdx.x;
    const float* x = in + (long long)s * Q_LORA;
    float* o = outp + (long long)s * Q_LORA;

    __shared__ float red[256];
    float ss = 0.0f;
    for (int i = threadIdx.x; i < Q_LORA; i += 256) { float v = x[i]; ss += v * v; }
    red[threadIdx.x] = ss; __syncthreads();
    for (int st = 128; st > 0; st >>= 1) {
        if (threadIdx.x < st) red[threadIdx.x] += red[threadIdx.x + st];
        __syncthreads();
    }
    float scale = rsqrtf(red[0] / (float)Q_LORA + 1e-6f);
    for (int i = threadIdx.x; i < Q_LORA; i += 256)
        o[i] = x[i] * scale * w[i];
}

// ---------------- RoPE on q_pe, scatter into q_full rope columns ----------------
__global__ void rope_q_kernel(const float* __restrict__ qpe,
                              const int*   __restrict__ pos_ids,
                              float* __restrict__ qfull)
{
    int s = blockIdx.x;
    int h = blockIdx.y;
    int j = threadIdx.x;            // 0..31
    float pos  = (float)pos_ids[s];
    float invf = powf(10000.0f, -(float)(2 * j) / (float)ROPE_D);
    float ang  = pos * invf;
    float c = cosf(ang), sn = sinf(ang);
    const float* x = qpe + (long long)s * (NH * ROPE_D) + h * ROPE_D;
    float x0 = x[2 * j], x1 = x[2 * j + 1];
    float* out = qfull + ((long long)h * S_LEN + s) * CDIM + KV_LORA;
    out[j]                = x0 * c - x1 * sn;
    out[j + ROPE_D / 2]   = x1 * c + x0 * sn;
}

// ---------------- row softmax over logits [NH*S, S] ----------------
__global__ void softmax_kernel(float* __restrict__ logits)
{
    long long row = blockIdx.x;
    float* p = logits + row * S_LEN;
    int tid = threadIdx.x;

    float v[8];
    float m = -1e30f;
    #pragma unroll
    for (int i = 0; i < 8; i++) { v[i] = p[tid + i * 256]; m = fmaxf(m, v[i]); }

    __shared__ float red[256];
    red[tid] = m; __syncthreads();
    for (int st = 128; st > 0; st >>= 1) {
        if (tid < st) red[tid] = fmaxf(red[tid], red[tid + st]);
        __syncthreads();
    }
    m = red[0]; __syncthreads();

    float sum = 0.0f;
    #pragma unroll
    for (int i = 0; i < 8; i++) { v[i] = __expf(v[i] - m); sum += v[i]; }
    red[tid] = sum; __syncthreads();
    for (int st = 128; st > 0; st >>= 1) {
        if (tid < st) red[tid] += red[tid + st];
        __syncthreads();
    }
    float inv = 1.0f / red[0];
    #pragma unroll
    for (int i = 0; i < 8; i++) p[tid + i * 256] = v[i] * inv;
}

// ---------------- host launcher ----------------
static void launch_gemm(bool transb, const float* A, const float* B, float* C,
                        int M, int N, int K, int lda, int ldb, int ldc,
                        long long sA, long long sB, long long sC,
                        int batch, float alpha, int mode)
{
    dim3 grid((N + BN - 1) / BN, M / BM, batch);
    if (transb)
        gemm_tc_kernel<true><<<grid, 256>>>(A, B, C, M, N, K, lda, ldb, ldc, sA, sB, sC, alpha, mode);
    else
        gemm_tc_kernel<false><<<grid, 256>>>(A, B, C, M, N, K, lda, ldb, ldc, sA, sB, sC, alpha, mode);
}

extern "C" void kernel_launch(void* const* d_in, const int* in_sizes, int n_in,
                              void* d_out, int out_size)
{
    (void)in_sizes; (void)n_in; (void)out_size;
    const float* X        = (const float*)d_in[0];   // [S, HID]
    const int*   pos      = (const int*)d_in[2];     // [1, S]
    const float* W_kv_a   = (const float*)d_in[3];   // [HID, CDIM]
    const float* W_q_a    = (const float*)d_in[4];   // [HID, Q_LORA]
    const float* q_ln     = (const float*)d_in[5];   // [Q_LORA]
    const float* kv_ln    = (const float*)d_in[6];   // [KV_LORA]
    const float* q_rope_w = (const float*)d_in[7];   // [Q_LORA, NH*ROPE_D]
    const float* fusedqk  = (const float*)d_in[8];   // [NH, Q_LORA, KV_LORA]
    const float* v_up     = (const float*)d_in[9];   // [NH, KV_LORA, V_D]
    const float* W_o      = (const float*)d_in[10];  // [NH*V_D, HID]
    float* out = (float*)d_out;                      // [S, HID]

    float *comp, *qa_pre, *qa, *qpe, *kfull, *qfull, *logits, *ctx, *attnout;
    cudaGetSymbolAddress((void**)&comp,    g_compressed);
    cudaGetSymbolAddress((void**)&qa_pre,  g_qa_pre);
    cudaGetSymbolAddress((void**)&qa,      g_qa);
    cudaGetSymbolAddress((void**)&qpe,     g_qpe);
    cudaGetSymbolAddress((void**)&kfull,   g_kfull);
    cudaGetSymbolAddress((void**)&qfull,   g_qfull);
    cudaGetSymbolAddress((void**)&logits,  g_logits);
    cudaGetSymbolAddress((void**)&ctx,     g_ctx);
    cudaGetSymbolAddress((void**)&attnout, g_attnout);

    const float scale = 1.0f / sqrtf(192.0f);   // 1/sqrt(NOPE_D + ROPE_D)

    // 1) compressed = X @ W_kv_a                      [S, CDIM]
    launch_gemm(false, X, W_kv_a, comp, S_LEN, CDIM, HID, HID, CDIM, CDIM, 0, 0, 0, 1, 1.0f, 0);
    // 2) qa_pre = X @ W_q_a                           [S, Q_LORA]
    launch_gemm(false, X, W_q_a, qa_pre, S_LEN, Q_LORA, HID, HID, Q_LORA, Q_LORA, 0, 0, 0, 1, 1.0f, 0);
    // 3) k_full = concat(rmsnorm(kva), rope(k_pe))    [S, CDIM]
    kva_rms_rope_kernel<<<S_LEN, 128>>>(comp, kv_ln, pos, kfull);
    // 4) qa = rmsnorm(qa_pre)                         [S, Q_LORA]
    qa_rms_kernel<<<S_LEN, 256>>>(qa_pre, q_ln, qa);
    // 5) qpe = qa @ q_rope_w                          [S, NH*ROPE_D]
    launch_gemm(false, qa, q_rope_w, qpe, S_LEN, NH * ROPE_D, Q_LORA,
                Q_LORA, NH * ROPE_D, NH * ROPE_D, 0, 0, 0, 1, 1.0f, 0);
    // 6) rope(q_pe) -> q_full[:, :, 512:576]
    rope_q_kernel<<<dim3(S_LEN, NH), ROPE_D / 2>>>(qpe, pos, qfull);
    // 7) dq = qa @ fusedqk[h] -> q_full[:, :, :512]   (batched over heads)
    launch_gemm(false, qa, fusedqk, qfull, S_LEN, KV_LORA, Q_LORA,
                Q_LORA, KV_LORA, CDIM,
                0, (long long)Q_LORA * KV_LORA, (long long)S_LEN * CDIM,
                NH, 1.0f, 0);
    // 8) logits = scale * q_full @ k_full^T, causal   (batched, TRANSB)
    launch_gemm(true, qfull, kfull, logits, S_LEN, S_LEN, CDIM,
                CDIM, CDIM, S_LEN,
                (long long)S_LEN * CDIM, 0, (long long)S_LEN * S_LEN,
                NH, scale, 1);
    // 9) softmax rows
    softmax_kernel<<<NH * S_LEN, 256>>>(logits);
    // 10) ctx = probs @ kva  (V = first 512 cols of k_full), causal K-limit
    launch_gemm(false, logits, kfull, ctx, S_LEN, KV_LORA, S_LEN,
                S_LEN, CDIM, KV_LORA,
                (long long)S_LEN * S_LEN, 0, (long long)S_LEN * KV_LORA,
                NH, 1.0f, 2);
    // 11) attnout[:, h*128:(h+1)*128] = ctx[h] @ v_up[h]
    launch_gemm(false, ctx, v_up, attnout, S_LEN, V_D, KV_LORA,
                KV_LORA, V_D, NH * V_D,
                (long long)S_LEN * KV_LORA, (long long)KV_LORA * V_D, (long long)V_D,
                NH, 1.0f, 0);
    // 12) out = attnout @ W_o                          [S, HID]
    launch_gemm(false, attnout, W_o, out, S_LEN, HID, NH * V_D,
                NH * V_D, HID, HID, 0, 0, 0, 1, 1.0f, 0);
}